// round 15
// baseline (speedup 1.0000x reference)
#include <cuda_runtime.h>
#include <math.h>

// ---------------- problem constants ----------------
#define SP      32768          // 32*32*32 spatial
#define EPSV    1e-5f
#define TN      64             // n-tile in context kernel
#define NCHUNK  16
#define CHUNK_N (SP / NCHUNK)  // 2048

// ---------------- scratch (device globals, no allocs) ----------------
__device__ float g_chanSum[3 * 2 * 256];
__device__ float g_chanSqs[3 * 2 * 256];
__device__ float g_chanMin[2 * 256];
__device__ float g_chanMax[2 * 256];
__device__ float g_scale[3 * 2 * 256];     // s  per tensor,b,c
__device__ float g_shift[3 * 2 * 256];     // t  per tensor,b,c
__device__ float g_rowmax[2 * 256];        // softmax row max for k
__device__ float g_ctx[2 * 4 * 64 * 64];   // unnormalized context
__device__ float g_Z[2 * 4 * 64];          // softmax denominators
__device__ float g_M[2 * 256 * 256];       // fused attention+1x1 matrix
__device__ float g_u[2 * 256];             // constant channel term
__device__ float g_W2[2 * 3 * 27 * 256];   // folded dg-conv weights
__device__ float g_ct[2 * 3 * 27];         // folded per-tap constants
__device__ float g_dg[2 * 3 * SP];         // dg conv output (pre-upsample)

// ---------------- f32x2 helpers (Blackwell packed fp32) ----------------
__device__ __forceinline__ unsigned long long pack2(float lo, float hi) {
    unsigned long long r;
    asm("mov.b64 %0, {%1, %2};" : "=l"(r) : "f"(lo), "f"(hi));
    return r;
}
__device__ __forceinline__ unsigned long long dup2(float v) {
    unsigned long long r;
    asm("mov.b64 %0, {%1, %1};" : "=l"(r) : "f"(v));
    return r;
}
__device__ __forceinline__ void fma2(unsigned long long& d, unsigned long long a,
                                     unsigned long long b) {
    asm("fma.rn.f32x2 %0, %1, %2, %0;" : "+l"(d) : "l"(a), "l"(b));
}
__device__ __forceinline__ void add2(unsigned long long& d, unsigned long long a) {
    asm("add.rn.f32x2 %0, %1, %0;" : "+l"(d) : "l"(a));
}
__device__ __forceinline__ void unpack2(unsigned long long v, float& lo, float& hi) {
    asm("mov.b64 {%0, %1}, %2;" : "=f"(lo), "=f"(hi) : "l"(v));
}

// ---------------- K0: zero accumulators ----------------
__global__ void k_zero() {
    int i = blockIdx.x * 256 + threadIdx.x;
    if (i < 2 * 3 * SP)      g_dg[i]  = 0.f;
    if (i < 2 * 4 * 64 * 64) g_ctx[i] = 0.f;
    if (i < 2 * 4 * 64)      g_Z[i]   = 0.f;
}

// ---------------- K1: per-channel stats (sum, sumsq, min, max) ----------------
__global__ void __launch_bounds__(256) k_stats(const float* __restrict__ q,
                                               const float* __restrict__ k,
                                               const float* __restrict__ v) {
    int bid = blockIdx.x;          // t*512 + b*256 + c
    int t   = bid >> 9;
    int bc  = bid & 511;
    const float* x = (t == 0 ? q : (t == 1 ? k : v)) + (size_t)bc * SP;
    int tid = threadIdx.x;
    float s = 0.f, s2 = 0.f, mn = 3.4e38f, mx = -3.4e38f;
    #pragma unroll 8
    for (int i = tid; i < SP; i += 256) {
        float val = x[i];
        s += val; s2 = fmaf(val, val, s2);
        mn = fminf(mn, val); mx = fmaxf(mx, val);
    }
    __shared__ float rs[256], rs2[256], rmn[256], rmx[256];
    rs[tid] = s; rs2[tid] = s2; rmn[tid] = mn; rmx[tid] = mx;
    __syncthreads();
    for (int o = 128; o > 0; o >>= 1) {
        if (tid < o) {
            rs[tid] += rs[tid + o]; rs2[tid] += rs2[tid + o];
            rmn[tid] = fminf(rmn[tid], rmn[tid + o]);
            rmx[tid] = fmaxf(rmx[tid], rmx[tid + o]);
        }
        __syncthreads();
    }
    if (tid == 0) {
        g_chanSum[bid] = rs[0];
        g_chanSqs[bid] = rs2[0];
        if (t == 1) { g_chanMin[bc] = rmn[0]; g_chanMax[bc] = rmx[0]; }
    }
}

// ---------------- K2: finalize GN affine + softmax row max ----------------
__global__ void k_norm_finalize(const float* __restrict__ gnw,
                                const float* __restrict__ gnb) {
    __shared__ float mu_s[3][2][4], rstd_s[3][2][4];
    int tid = threadIdx.x;
    if (tid < 24) {
        int t = tid >> 3, b = (tid >> 2) & 1, g = tid & 3;
        float s = 0.f, s2 = 0.f;
        int base = t * 512 + b * 256 + g * 64;
        for (int c = 0; c < 64; c++) { s += g_chanSum[base + c]; s2 += g_chanSqs[base + c]; }
        float n   = 64.0f * (float)SP;
        float mu  = s / n;
        float var = s2 / n - mu * mu;
        mu_s[t][b][g]   = mu;
        rstd_s[t][b][g] = rsqrtf(var + EPSV);
    }
    __syncthreads();
    int c = tid;           // 0..255
    int g = c >> 6;
    for (int t = 0; t < 3; t++)
        for (int b = 0; b < 2; b++) {
            float sc = gnw[c] * rstd_s[t][b][g];
            float sh = gnb[c] - mu_s[t][b][g] * sc;
            int idx = t * 512 + b * 256 + c;
            g_scale[idx] = sc;
            g_shift[idx] = sh;
            if (t == 1) {
                float rm = (sc >= 0.f) ? sc * g_chanMax[b * 256 + c]
                                       : sc * g_chanMin[b * 256 + c];
                g_rowmax[b * 256 + c] = rm + sh;
            }
        }
}

// ---------------- K3: context GEMM (64x64 per (b,h)) + softmax Z ----------------
__global__ void __launch_bounds__(256) k_context(const float* __restrict__ kin,
                                                 const float* __restrict__ vin) {
    int blk   = blockIdx.x;                 // ((b*4+h)*NCHUNK + chunk)
    int chunk = blk & (NCHUNK - 1);
    int bh    = blk >> 4;                   // b*4+h
    int b     = bh >> 2, h = bh & 3;
    int tid   = threadIdx.x;

    __shared__ __align__(16) float skm[TN * 68];   // exp(nk) tile, layout [n][d]
    __shared__ __align__(16) float svm[TN * 68];   // nv tile,      layout [n][d]
    __shared__ float sK[64], cK[64], sV[64], cV[64];
    __shared__ float zred[64 * 16];

    if (tid < 64) {
        int ch  = h * 64 + tid;
        int idx = b * 256 + ch;
        sK[tid] = g_scale[512 + idx];
        cK[tid] = g_shift[512 + idx] - g_rowmax[idx];
        sV[tid] = g_scale[1024 + idx];
        cV[tid] = g_shift[1024 + idx];
    }
    __syncthreads();

    const float* kbase = kin + ((size_t)(b * 256 + h * 64)) * SP + chunk * CHUNK_N;
    const float* vbase = vin + ((size_t)(b * 256 + h * 64)) * SP + chunk * CHUNK_N;

    int ty = tid >> 4, tx = tid & 15;
    int d0 = ty * 4,   e0 = tx * 4;

    unsigned long long acc[2][4];
    #pragma unroll
    for (int i = 0; i < 2; i++)
        #pragma unroll
        for (int j = 0; j < 4; j++) acc[i][j] = 0ull;
    unsigned long long zacc0 = 0ull, zacc1 = 0ull;

    for (int n0 = 0; n0 < CHUNK_N; n0 += TN) {
        #pragma unroll
        for (int i = 0; i < 16; i++) {
            int idx = tid + i * 256;
            int d = idx >> 6, n = idx & 63;
            float kv = kbase[(size_t)d * SP + n0 + n];
            float vv = vbase[(size_t)d * SP + n0 + n];
            skm[n * 68 + d] = __expf(fmaf(sK[d], kv, cK[d]));
            svm[n * 68 + d] = fmaf(sV[d], vv, cV[d]);
        }
        __syncthreads();
        #pragma unroll 4
        for (int n = 0; n < TN; n++) {
            float4 a  = *reinterpret_cast<const float4*>(&skm[n * 68 + d0]);
            float4 vv = *reinterpret_cast<const float4*>(&svm[n * 68 + e0]);
            unsigned long long a01 = pack2(a.x, a.y);
            unsigned long long a23 = pack2(a.z, a.w);
            unsigned long long v0 = dup2(vv.x), v1 = dup2(vv.y);
            unsigned long long v2 = dup2(vv.z), v3 = dup2(vv.w);
            fma2(acc[0][0], a01, v0); fma2(acc[0][1], a01, v1);
            fma2(acc[0][2], a01, v2); fma2(acc[0][3], a01, v3);
            fma2(acc[1][0], a23, v0); fma2(acc[1][1], a23, v1);
            fma2(acc[1][2], a23, v2); fma2(acc[1][3], a23, v3);
            if ((n >> 2) == tx) { add2(zacc0, a01); add2(zacc1, a23); }
        }
        __syncthreads();
    }

    // reduce Z
    {
        float lo, hi;
        unpack2(zacc0, lo, hi);
        zred[(d0 + 0) * 16 + tx] = lo; zred[(d0 + 1) * 16 + tx] = hi;
        unpack2(zacc1, lo, hi);
        zred[(d0 + 2) * 16 + tx] = lo; zred[(d0 + 3) * 16 + tx] = hi;
    }
    __syncthreads();
    if (tid < 64) {
        float s = 0.f;
        #pragma unroll
        for (int i = 0; i < 16; i++) s += zred[tid * 16 + i];
        atomicAdd(&g_Z[bh * 64 + tid], s);
    }
    // accumulate context
    #pragma unroll
    for (int i = 0; i < 2; i++)
        #pragma unroll
        for (int j = 0; j < 4; j++) {
            float lo, hi;
            unpack2(acc[i][j], lo, hi);
            int e = e0 + j;
            atomicAdd(&g_ctx[(bh * 64 + d0 + 2 * i)     * 64 + e], lo);
            atomicAdd(&g_ctx[(bh * 64 + d0 + 2 * i + 1) * 64 + e], hi);
        }
}

// ---------------- K4a: M[b,o,c] = sum_e outw[o,h*64+e]*ctx[b,h,d,e]/Z ; u[b,o] ----------------
__global__ void __launch_bounds__(256) k_Mu(const float* __restrict__ outw,
                                            const float* __restrict__ outb) {
    int b = blockIdx.x >> 8, o = blockIdx.x & 255;
    int c = threadIdx.x;
    __shared__ float wrow[256];
    wrow[c] = outw[o * 256 + c];
    __syncthreads();
    int h = c >> 6, d = c & 63;
    const float* ctxrow = &g_ctx[((b * 4 + h) * 64 + d) * 64];
    float zinv = 1.0f / g_Z[(b * 4 + h) * 64 + d];
    float m = 0.f;
    #pragma unroll 8
    for (int e = 0; e < 64; e++) m = fmaf(wrow[h * 64 + e], ctxrow[e], m);
    m *= zinv;
    g_M[(b * 256 + o) * 256 + c] = m;

    __shared__ float red[256];
    red[c] = m * g_shift[b * 256 + c];          // t_q
    __syncthreads();
    for (int s = 128; s > 0; s >>= 1) {
        if (c < s) red[c] += red[c + s];
        __syncthreads();
    }
    if (c == 0) g_u[b * 256 + o] = outb[o] + red[0];
}

// ---------------- K4b: folded weights W2 and per-tap constants ct ----------------
__global__ void __launch_bounds__(256) k_W2ct(const float* __restrict__ dgw) {
    int bi = blockIdx.x;               // (b*3+j)*27 + t
    int t  = bi % 27;
    int bj = bi / 27;
    int b  = bj / 3, j = bj % 3;
    int c  = threadIdx.x;
    __shared__ float dcol[256];
    dcol[c] = dgw[(j * 256 + c) * 27 + t];
    __syncthreads();
    const float* Mp = &g_M[b * 256 * 256 + c];
    float a = 0.f;
    #pragma unroll 4
    for (int o = 0; o < 256; o++) a = fmaf(dcol[o], Mp[o * 256], a);
    g_W2[((b * 3 + j) * 27 + t) * 256 + c] = dcol[c] + g_scale[b * 256 + c] * a;

    __shared__ float red[256];
    red[c] = dcol[c] * g_u[b * 256 + c];
    __syncthreads();
    for (int s = 128; s > 0; s >>= 1) {
        if (c < s) red[c] += red[c + s];
        __syncthreads();
    }
    if (c == 0) g_ct[(b * 3 + j) * 27 + t] = red[0];
}

// ---------------- K5: folded 3x3x3 conv over raw q -> g_dg ----------------
__global__ void __launch_bounds__(512) k_dgconv(const float* __restrict__ q,
                                                const float* __restrict__ dgbias) {
    int bx = blockIdx.x;               // b(2) * ztile(8) * ytile(4)
    int b  = bx >> 5;
    int r  = bx & 31;
    int z0 = (r >> 2) * 4;
    int y0 = (r & 3) * 8;
    int cg = blockIdx.y;               // 0..3, 64 channels each

    __shared__ float qs[4 * 6 * 10 * 34];        // 4ch x 6z x 10y x 34x
    __shared__ unsigned long long wps[27 * 4];   // packed {w_j0, w_j1}
    __shared__ float w2s[27 * 4];                // w_j2
    __shared__ float cts[3 * 27];

    int tid = threadIdx.x;
    int x  = tid & 31;
    int yy = (tid >> 5) & 3;
    int zz = tid >> 7;

    if (tid < 81) cts[tid] = g_ct[b * 81 + tid];

    unsigned long long accP0 = 0ull, accP1 = 0ull;
    float accS0 = 0.f, accS1 = 0.f;

    for (int ch = 0; ch < 16; ch++) {
        int cbase = cg * 64 + ch * 4;
        __syncthreads();
        if (tid < 108) {
            int t = tid >> 2, cc = tid & 3;
            int c = cbase + cc;
            float w0 = g_W2[((b * 3 + 0) * 27 + t) * 256 + c];
            float w1 = g_W2[((b * 3 + 1) * 27 + t) * 256 + c];
            float w2 = g_W2[((b * 3 + 2) * 27 + t) * 256 + c];
            wps[tid] = pack2(w0, w1);
            w2s[tid] = w2;
        }
        for (int it = tid; it < 8160; it += 512) {
            int c  = it / 2040;
            int r2 = it - c * 2040;
            int lz = r2 / 340;
            int r3 = r2 - lz * 340;
            int ly = r3 / 34;
            int lx = r3 - ly * 34;
            int gz = z0 - 1 + lz, gy = y0 - 1 + ly, gx = lx - 1;
            float val = 0.f;
            if ((unsigned)gz < 32u && (unsigned)gy < 32u && (unsigned)gx < 32u)
                val = q[((size_t)(b * 256 + cbase + c)) * SP + gz * 1024 + gy * 32 + gx];
            qs[it] = val;
        }
        __syncthreads();

        const float* qp = &qs[(zz * 10 + yy) * 34 + x];
        #pragma unroll
        for (int cc = 0; cc < 4; cc++) {
            #pragma unroll
            for (int kz = 0; kz < 3; kz++) {
                #pragma unroll
                for (int ky = 0; ky < 3; ky++) {
                    #pragma unroll
                    for (int kx = 0; kx < 3; kx++) {
                        int t = (kz * 3 + ky) * 3 + kx;
                        int off = ((cc * 6 + kz) * 10 + ky) * 34 + kx;
                        float q0 = qp[off];
                        float q1 = qp[off + 4 * 34];
                        unsigned long long wpp = wps[t * 4 + cc];
                        float w2 = w2s[t * 4 + cc];
                        fma2(accP0, dup2(q0), wpp);
                        fma2(accP1, dup2(q1), wpp);
                        accS0 = fmaf(q0, w2, accS0);
                        accS1 = fmaf(q1, w2, accS1);
                    }
                }
            }
        }
    }

    int z  = z0 + zz;
    int ya = y0 + yy, yb = y0 + yy + 4;
    float out0[3], out1[3];
    unpack2(accP0, out0[0], out0[1]); out0[2] = accS0;
    unpack2(accP1, out1[0], out1[1]); out1[2] = accS1;

    if (cg == 0) {
        // bias + in-bounds per-tap constants
        for (int j = 0; j < 3; j++) {
            float s0 = dgbias[j], s1 = dgbias[j];
            for (int kz = 0; kz < 3; kz++) {
                int gz = z + kz - 1;
                if ((unsigned)gz >= 32u) continue;
                for (int ky = 0; ky < 3; ky++) {
                    int gya = ya + ky - 1, gyb = yb + ky - 1;
                    bool oka = (unsigned)gya < 32u, okb = (unsigned)gyb < 32u;
                    for (int kx = 0; kx < 3; kx++) {
                        int gx = x + kx - 1;
                        if ((unsigned)gx >= 32u) continue;
                        float ctv = cts[j * 27 + (kz * 3 + ky) * 3 + kx];
                        if (oka) s0 += ctv;
                        if (okb) s1 += ctv;
                    }
                }
            }
            out0[j] += s0;
            out1[j] += s1;
        }
    }
    for (int j = 0; j < 3; j++) {
        atomicAdd(&g_dg[(b * 3 + j) * SP + z * 1024 + ya * 32 + x], out0[j]);
        atomicAdd(&g_dg[(b * 3 + j) * SP + z * 1024 + yb * 32 + x], out1[j]);
    }
}

// ---------------- K6: nearest 2x upsample fused with final 3x3x3 conv ----------------
__global__ void __launch_bounds__(256) k_upconv(const float* __restrict__ nlw,
                                                const float* __restrict__ nlb,
                                                float* __restrict__ out) {
    __shared__ float w[243];
    __shared__ float bsh[3];
    int tid = threadIdx.x;
    if (tid < 243) w[tid] = nlw[tid];
    if (tid < 3)   bsh[tid] = nlb[tid];
    __syncthreads();
    int gid = blockIdx.x * 256 + tid;        // 524288 total
    int b   = gid >> 18;
    int rem = gid & 262143;
    int z = rem >> 12, y = (rem >> 6) & 63, x = rem & 63;
    float a0 = bsh[0], a1 = bsh[1], a2 = bsh[2];
    const float* dgp = &g_dg[b * 3 * SP];
    #pragma unroll
    for (int kz = 0; kz < 3; kz++) {
        int zu = z + kz - 1;
        if ((unsigned)zu >= 64u) continue;
        int szo = (zu >> 1) * 1024;
        #pragma unroll
        for (int ky = 0; ky < 3; ky++) {
            int yu = y + ky - 1;
            if ((unsigned)yu >= 64u) continue;
            int syo = szo + (yu >> 1) * 32;
            #pragma unroll
            for (int kx = 0; kx < 3; kx++) {
                int xu = x + kx - 1;
                if ((unsigned)xu >= 64u) continue;
                int s = syo + (xu >> 1);
                int t = (kz * 3 + ky) * 3 + kx;
                float v0 = dgp[s];
                float v1 = dgp[s + SP];
                float v2 = dgp[s + 2 * SP];
                a0 = fmaf(w[t],       v0, a0);
                a0 = fmaf(w[27 + t],  v1, a0);
                a0 = fmaf(w[54 + t],  v2, a0);
                a1 = fmaf(w[81 + t],  v0, a1);
                a1 = fmaf(w[108 + t], v1, a1);
                a1 = fmaf(w[135 + t], v2, a1);
                a2 = fmaf(w[162 + t], v0, a2);
                a2 = fmaf(w[189 + t], v1, a2);
                a2 = fmaf(w[216 + t], v2, a2);
            }
        }
    }
    int obase = z * 4096 + y * 64 + x;       // 64^3 layout
    out[(b * 3 + 0) * 262144 + obase] = a0;
    out[(b * 3 + 1) * 262144 + obase] = a1;
    out[(b * 3 + 2) * 262144 + obase] = a2;
}

// ---------------- launcher ----------------
extern "C" void kernel_launch(void* const* d_in, const int* in_sizes, int n_in,
                              void* d_out, int out_size) {
    const float* q    = (const float*)d_in[0];
    const float* k    = (const float*)d_in[1];
    const float* v    = (const float*)d_in[2];
    const float* gnw  = (const float*)d_in[3];
    const float* gnb  = (const float*)d_in[4];
    const float* outw = (const float*)d_in[5];
    const float* outb = (const float*)d_in[6];
    const float* dgw  = (const float*)d_in[7];
    const float* dgb  = (const float*)d_in[8];
    const float* nlw  = (const float*)d_in[9];
    const float* nlb  = (const float*)d_in[10];
    float* out = (float*)d_out;

    k_zero<<<768, 256>>>();
    k_stats<<<1536, 256>>>(q, k, v);
    k_norm_finalize<<<1, 256>>>(gnw, gnb);
    k_context<<<128, 256>>>(k, v);
    k_Mu<<<512, 256>>>(outw, outb);
    k_W2ct<<<162, 256>>>(dgw);
    dim3 g5(64, 4);
    k_dgconv<<<g5, 512>>>(q, dgb);
    k_upconv<<<2048, 256>>>(nlw, nlb, out);
}

// round 16
// speedup vs baseline: 2.2015x; 2.2015x over previous
#include <cuda_runtime.h>
#include <math.h>

// ---------------- problem constants ----------------
#define SP      32768          // 32*32*32 spatial
#define EPSV    1e-5f
#define TN      64             // n-tile in context kernel
#define NCHUNK  64
#define CHUNK_N (SP / NCHUNK)  // 512

// ---------------- scratch (device globals, no allocs) ----------------
__device__ float g_chanSum[3 * 2 * 256];
__device__ float g_chanSqs[3 * 2 * 256];
__device__ float g_chanMin[2 * 256];
__device__ float g_chanMax[2 * 256];
__device__ float g_scale[3 * 2 * 256];
__device__ float g_shift[3 * 2 * 256];
__device__ float g_rowmax[2 * 256];
__device__ float g_ctx[2 * 4 * 64 * 64];
__device__ float g_Z[2 * 4 * 64];
__device__ float g_M[2 * 256 * 256];
__device__ float g_u[2 * 256];
__device__ float g_W2[2 * 3 * 27 * 256];
__device__ float g_ct[2 * 3 * 27];
__device__ float g_dg[2 * 3 * SP];

// ---------------- f32x2 helpers ----------------
__device__ __forceinline__ unsigned long long pack2(float lo, float hi) {
    unsigned long long r;
    asm("mov.b64 %0, {%1, %2};" : "=l"(r) : "f"(lo), "f"(hi));
    return r;
}
__device__ __forceinline__ unsigned long long dup2(float v) {
    unsigned long long r;
    asm("mov.b64 %0, {%1, %1};" : "=l"(r) : "f"(v));
    return r;
}
__device__ __forceinline__ void fma2(unsigned long long& d, unsigned long long a,
                                     unsigned long long b) {
    asm("fma.rn.f32x2 %0, %1, %2, %0;" : "+l"(d) : "l"(a), "l"(b));
}
__device__ __forceinline__ void add2(unsigned long long& d, unsigned long long a) {
    asm("add.rn.f32x2 %0, %1, %0;" : "+l"(d) : "l"(a));
}
__device__ __forceinline__ void unpack2(unsigned long long v, float& lo, float& hi) {
    asm("mov.b64 {%0, %1}, %2;" : "=f"(lo), "=f"(hi) : "l"(v));
}

// ---------------- K0: zero accumulators ----------------
__global__ void k_zero() {
    int i = blockIdx.x * 256 + threadIdx.x;
    if (i < 2 * 3 * SP)      g_dg[i]  = 0.f;
    if (i < 2 * 4 * 64 * 64) g_ctx[i] = 0.f;
    if (i < 2 * 4 * 64)      g_Z[i]   = 0.f;
}

// ---------------- K1: per-channel stats, float4 ----------------
__global__ void __launch_bounds__(256) k_stats(const float* __restrict__ q,
                                               const float* __restrict__ k,
                                               const float* __restrict__ v) {
    int bid = blockIdx.x;          // t*512 + b*256 + c
    int t   = bid >> 9;
    int bc  = bid & 511;
    const float* xp = (t == 0 ? q : (t == 1 ? k : v)) + (size_t)bc * SP;
    const float4* x4 = reinterpret_cast<const float4*>(xp);
    int tid = threadIdx.x;
    float s = 0.f, s2 = 0.f, mn = 3.4e38f, mx = -3.4e38f;
    #pragma unroll 4
    for (int i = tid; i < SP / 4; i += 256) {
        float4 u = x4[i];
        s += (u.x + u.y) + (u.z + u.w);
        s2 = fmaf(u.x, u.x, s2); s2 = fmaf(u.y, u.y, s2);
        s2 = fmaf(u.z, u.z, s2); s2 = fmaf(u.w, u.w, s2);
        mn = fminf(mn, fminf(fminf(u.x, u.y), fminf(u.z, u.w)));
        mx = fmaxf(mx, fmaxf(fmaxf(u.x, u.y), fmaxf(u.z, u.w)));
    }
    __shared__ float rs[256], rs2[256], rmn[256], rmx[256];
    rs[tid] = s; rs2[tid] = s2; rmn[tid] = mn; rmx[tid] = mx;
    __syncthreads();
    for (int o = 128; o > 0; o >>= 1) {
        if (tid < o) {
            rs[tid] += rs[tid + o]; rs2[tid] += rs2[tid + o];
            rmn[tid] = fminf(rmn[tid], rmn[tid + o]);
            rmx[tid] = fmaxf(rmx[tid], rmx[tid + o]);
        }
        __syncthreads();
    }
    if (tid == 0) {
        g_chanSum[bid] = rs[0];
        g_chanSqs[bid] = rs2[0];
        if (t == 1) { g_chanMin[bc] = rmn[0]; g_chanMax[bc] = rmx[0]; }
    }
}

// ---------------- K2: finalize GN affine + softmax row max ----------------
__global__ void k_norm_finalize(const float* __restrict__ gnw,
                                const float* __restrict__ gnb) {
    __shared__ float mu_s[3][2][4], rstd_s[3][2][4];
    int tid = threadIdx.x;
    if (tid < 24) {
        int t = tid >> 3, b = (tid >> 2) & 1, g = tid & 3;
        float s = 0.f, s2 = 0.f;
        int base = t * 512 + b * 256 + g * 64;
        for (int c = 0; c < 64; c++) { s += g_chanSum[base + c]; s2 += g_chanSqs[base + c]; }
        float n   = 64.0f * (float)SP;
        float mu  = s / n;
        float var = s2 / n - mu * mu;
        mu_s[t][b][g]   = mu;
        rstd_s[t][b][g] = rsqrtf(var + EPSV);
    }
    __syncthreads();
    int c = tid;
    int g = c >> 6;
    for (int t = 0; t < 3; t++)
        for (int b = 0; b < 2; b++) {
            float sc = gnw[c] * rstd_s[t][b][g];
            float sh = gnb[c] - mu_s[t][b][g] * sc;
            int idx = t * 512 + b * 256 + c;
            g_scale[idx] = sc;
            g_shift[idx] = sh;
            if (t == 1) {
                float rm = (sc >= 0.f) ? sc * g_chanMax[b * 256 + c]
                                       : sc * g_chanMin[b * 256 + c];
                g_rowmax[b * 256 + c] = rm + sh;
            }
        }
}

// ---------------- K3: context GEMM (64x64 per (b,h)) + softmax Z ----------------
__global__ void __launch_bounds__(256, 3) k_context(const float* __restrict__ kin,
                                                    const float* __restrict__ vin) {
    int blk   = blockIdx.x;                 // bh*NCHUNK + chunk
    int chunk = blk & (NCHUNK - 1);
    int bh    = blk >> 6;                   // b*4+h
    int b     = bh >> 2, h = bh & 3;
    int tid   = threadIdx.x;

    __shared__ __align__(16) float skm[TN * 68];   // exp(nk), layout [n][d]
    __shared__ __align__(16) float svm[TN * 68];   // nv,      layout [n][d]
    __shared__ float sK[64], cK[64], sV[64], cV[64];
    __shared__ float zred[64 * 16];

    if (tid < 64) {
        int ch  = h * 64 + tid;
        int idx = b * 256 + ch;
        sK[tid] = g_scale[512 + idx];
        cK[tid] = g_shift[512 + idx] - g_rowmax[idx];
        sV[tid] = g_scale[1024 + idx];
        cV[tid] = g_shift[1024 + idx];
    }
    __syncthreads();

    const float* kbase = kin + ((size_t)(b * 256 + h * 64)) * SP + chunk * CHUNK_N;
    const float* vbase = vin + ((size_t)(b * 256 + h * 64)) * SP + chunk * CHUNK_N;

    int ty = tid >> 4, tx = tid & 15;
    int d0 = ty * 4,   e0 = tx * 4;

    unsigned long long acc[2][4];
    #pragma unroll
    for (int i = 0; i < 2; i++)
        #pragma unroll
        for (int j = 0; j < 4; j++) acc[i][j] = 0ull;
    unsigned long long z01 = 0ull, z23 = 0ull;

    for (int n0 = 0; n0 < CHUNK_N; n0 += TN) {
        #pragma unroll
        for (int i = 0; i < 16; i++) {
            int idx = tid + i * 256;
            int d = idx >> 6, n = idx & 63;
            float kv = kbase[(size_t)d * SP + n0 + n];
            float vv = vbase[(size_t)d * SP + n0 + n];
            skm[n * 68 + d] = __expf(fmaf(sK[d], kv, cK[d]));
            svm[n * 68 + d] = fmaf(sV[d], vv, cV[d]);
        }
        __syncthreads();
        #pragma unroll 4
        for (int n = 0; n < TN; n++) {
            ulonglong2 a = *reinterpret_cast<const ulonglong2*>(&skm[n * 68 + d0]);
            float4 vv    = *reinterpret_cast<const float4*>(&svm[n * 68 + e0]);
            unsigned long long v0 = dup2(vv.x), v1 = dup2(vv.y);
            unsigned long long v2 = dup2(vv.z), v3 = dup2(vv.w);
            fma2(acc[0][0], a.x, v0); fma2(acc[0][1], a.x, v1);
            fma2(acc[0][2], a.x, v2); fma2(acc[0][3], a.x, v3);
            fma2(acc[1][0], a.y, v0); fma2(acc[1][1], a.y, v1);
            fma2(acc[1][2], a.y, v2); fma2(acc[1][3], a.y, v3);
        }
        // Z partials out of the hot loop: thread sums n = 4tx..4tx+3 over rows d0..d0+3
        #pragma unroll
        for (int nn = 0; nn < 4; nn++) {
            ulonglong2 za = *reinterpret_cast<const ulonglong2*>(&skm[(tx * 4 + nn) * 68 + d0]);
            add2(z01, za.x); add2(z23, za.y);
        }
        __syncthreads();
    }

    {
        float lo, hi;
        unpack2(z01, lo, hi);
        zred[(d0 + 0) * 16 + tx] = lo; zred[(d0 + 1) * 16 + tx] = hi;
        unpack2(z23, lo, hi);
        zred[(d0 + 2) * 16 + tx] = lo; zred[(d0 + 3) * 16 + tx] = hi;
    }
    __syncthreads();
    if (tid < 64) {
        float s = 0.f;
        #pragma unroll
        for (int i = 0; i < 16; i++) s += zred[tid * 16 + i];
        atomicAdd(&g_Z[bh * 64 + tid], s);
    }
    #pragma unroll
    for (int i = 0; i < 2; i++)
        #pragma unroll
        for (int j = 0; j < 4; j++) {
            float lo, hi;
            unpack2(acc[i][j], lo, hi);
            int e = e0 + j;
            atomicAdd(&g_ctx[(bh * 64 + d0 + 2 * i)     * 64 + e], lo);
            atomicAdd(&g_ctx[(bh * 64 + d0 + 2 * i + 1) * 64 + e], hi);
        }
}

// ---------------- K4a: M[b,o,c] and u[b,o] ----------------
__global__ void __launch_bounds__(256) k_Mu(const float* __restrict__ outw,
                                            const float* __restrict__ outb) {
    int b = blockIdx.x >> 8, o = blockIdx.x & 255;
    int c = threadIdx.x;
    __shared__ float wrow[256];
    wrow[c] = outw[o * 256 + c];
    __syncthreads();
    int h = c >> 6, d = c & 63;
    const float* ctxrow = &g_ctx[((b * 4 + h) * 64 + d) * 64];
    float zinv = 1.0f / g_Z[(b * 4 + h) * 64 + d];
    float m = 0.f;
    #pragma unroll 8
    for (int e = 0; e < 64; e++) m = fmaf(wrow[h * 64 + e], ctxrow[e], m);
    m *= zinv;
    g_M[(b * 256 + o) * 256 + c] = m;

    __shared__ float red[256];
    red[c] = m * g_shift[b * 256 + c];
    __syncthreads();
    for (int s = 128; s > 0; s >>= 1) {
        if (c < s) red[c] += red[c + s];
        __syncthreads();
    }
    if (c == 0) g_u[b * 256 + o] = outb[o] + red[0];
}

// ---------------- K4b: folded weights W2 and per-tap constants ct ----------------
__global__ void __launch_bounds__(256) k_W2ct(const float* __restrict__ dgw) {
    int bi = blockIdx.x;               // (b*3+j)*27 + t
    int t  = bi % 27;
    int bj = bi / 27;
    int b  = bj / 3, j = bj % 3;
    int c  = threadIdx.x;
    __shared__ float dcol[256];
    dcol[c] = dgw[(j * 256 + c) * 27 + t];
    __syncthreads();
    const float* Mp = &g_M[b * 256 * 256 + c];
    float a = 0.f;
    #pragma unroll 4
    for (int o = 0; o < 256; o++) a = fmaf(dcol[o], Mp[o * 256], a);
    g_W2[((b * 3 + j) * 27 + t) * 256 + c] = dcol[c] + g_scale[b * 256 + c] * a;

    __shared__ float red[256];
    red[c] = dcol[c] * g_u[b * 256 + c];
    __syncthreads();
    for (int s = 128; s > 0; s >>= 1) {
        if (c < s) red[c] += red[c + s];
        __syncthreads();
    }
    if (c == 0) g_ct[(b * 3 + j) * 27 + t] = red[0];
}

// ---------------- K5: folded 3x3x3 conv over raw q -> g_dg ----------------
// 256 threads: x(32) x yq(2) x zz(4); each thread computes 4 y-points.
// All multiplies are packed f32x2 with pre-duplicated smem weights.
__global__ void __launch_bounds__(256) k_dgconv(const float* __restrict__ q,
                                                const float* __restrict__ dgbias) {
    int bx = blockIdx.x;               // b(2) * ztile(8) * ytile(4)
    int b  = bx >> 5;
    int r  = bx & 31;
    int z0 = (r >> 2) * 4;
    int y0 = (r & 3) * 8;
    int cg = blockIdx.y;               // 0..3

    __shared__ float  qs[4 * 6 * 10 * 34];
    __shared__ __align__(16) float4 wd4[27 * 4];   // {w0,w0,w1,w1}
    __shared__ __align__(8)  float2 w2d[27 * 4];   // {w2,w2}
    __shared__ float cts[3 * 27];

    int tid = threadIdx.x;
    int x  = tid & 31;
    int yq = (tid >> 5) & 1;
    int zz = tid >> 6;

    if (tid < 81) cts[tid] = g_ct[b * 81 + tid];

    unsigned long long acc[3][2];
    #pragma unroll
    for (int j = 0; j < 3; j++) { acc[j][0] = 0ull; acc[j][1] = 0ull; }

    for (int ch = 0; ch < 16; ch++) {
        int cbase = cg * 64 + ch * 4;
        __syncthreads();
        if (tid < 108) {
            int t = tid >> 2, cc = tid & 3;
            int c = cbase + cc;
            float w0 = g_W2[((b * 3 + 0) * 27 + t) * 256 + c];
            float w1 = g_W2[((b * 3 + 1) * 27 + t) * 256 + c];
            float w2 = g_W2[((b * 3 + 2) * 27 + t) * 256 + c];
            wd4[tid] = make_float4(w0, w0, w1, w1);
            w2d[tid] = make_float2(w2, w2);
        }
        for (int it = tid; it < 8160; it += 256) {
            int c  = it / 2040;
            int r2 = it - c * 2040;
            int lz = r2 / 340;
            int r3 = r2 - lz * 340;
            int ly = r3 / 34;
            int lx = r3 - ly * 34;
            int gz = z0 - 1 + lz, gy = y0 - 1 + ly, gx = lx - 1;
            float val = 0.f;
            if ((unsigned)gz < 32u && (unsigned)gy < 32u && (unsigned)gx < 32u)
                val = q[((size_t)(b * 256 + cbase + c)) * SP + gz * 1024 + gy * 32 + gx];
            qs[it] = val;
        }
        __syncthreads();

        #pragma unroll
        for (int cc = 0; cc < 4; cc++) {
            #pragma unroll
            for (int kz = 0; kz < 3; kz++) {
                const float* qb = &qs[((cc * 6 + zz + kz) * 10 + yq * 4) * 34 + x];
                #pragma unroll
                for (int kx = 0; kx < 3; kx++) {
                    float q0 = qb[kx];
                    float q1 = qb[34 + kx];
                    float q2 = qb[68 + kx];
                    float q3 = qb[102 + kx];
                    float q4 = qb[136 + kx];
                    float q5 = qb[170 + kx];
                    unsigned long long Q01 = pack2(q0, q1);
                    unsigned long long Q12 = pack2(q1, q2);
                    unsigned long long Q23 = pack2(q2, q3);
                    unsigned long long Q34 = pack2(q3, q4);
                    unsigned long long Q45 = pack2(q4, q5);
                    #pragma unroll
                    for (int ky = 0; ky < 3; ky++) {
                        int wi = ((kz * 3 + ky) * 3 + kx) * 4 + cc;
                        ulonglong2 wu = *reinterpret_cast<const ulonglong2*>(&wd4[wi]);
                        unsigned long long w2u =
                            *reinterpret_cast<const unsigned long long*>(&w2d[wi]);
                        unsigned long long A = (ky == 0) ? Q01 : (ky == 1) ? Q12 : Q23;
                        unsigned long long B = (ky == 0) ? Q23 : (ky == 1) ? Q34 : Q45;
                        fma2(acc[0][0], A, wu.x); fma2(acc[0][1], B, wu.x);
                        fma2(acc[1][0], A, wu.y); fma2(acc[1][1], B, wu.y);
                        fma2(acc[2][0], A, w2u);  fma2(acc[2][1], B, w2u);
                    }
                }
            }
        }
    }

    int z = z0 + zz;
    float o[3][4];
    #pragma unroll
    for (int j = 0; j < 3; j++) {
        unpack2(acc[j][0], o[j][0], o[j][1]);
        unpack2(acc[j][1], o[j][2], o[j][3]);
    }

    if (cg == 0) {
        for (int j = 0; j < 3; j++)
            for (int py = 0; py < 4; py++) {
                int y = y0 + yq * 4 + py;
                float s = dgbias[j];
                for (int kz = 0; kz < 3; kz++) {
                    int gz = z + kz - 1;
                    if ((unsigned)gz >= 32u) continue;
                    for (int ky = 0; ky < 3; ky++) {
                        int gy = y + ky - 1;
                        if ((unsigned)gy >= 32u) continue;
                        for (int kx = 0; kx < 3; kx++) {
                            int gx = x + kx - 1;
                            if ((unsigned)gx >= 32u) continue;
                            s += cts[j * 27 + (kz * 3 + ky) * 3 + kx];
                        }
                    }
                }
                o[j][py] += s;
            }
    }
    #pragma unroll
    for (int j = 0; j < 3; j++)
        #pragma unroll
        for (int py = 0; py < 4; py++) {
            int y = y0 + yq * 4 + py;
            atomicAdd(&g_dg[(b * 3 + j) * SP + z * 1024 + y * 32 + x], o[j][py]);
        }
}

// ---------------- K6: fused 2x nearest-upsample + final 3x3x3 conv ----------------
// Parity identity: per axis, output o touches only inputs base+{0,1},
// base = ((o+1)>>1)-1, with combined weights by (parity, offset).
// Dropped boundary taps correspond exactly to OOB input cells (loaded as 0).
__global__ void __launch_bounds__(256) k_upconv(const float* __restrict__ nlw,
                                                const float* __restrict__ nlb,
                                                float* __restrict__ out) {
    __shared__ float cw[576];     // [par(8)][off(8)][jc(9)]
    __shared__ float bsm[3];
    int tid = threadIdx.x;
    if (tid < 3) bsm[tid] = nlb[tid];
    for (int e = tid; e < 576; e += 256) {
        int jc  = e % 9;
        int off = (e / 9) & 7;
        int par = e / 72;
        int pz = (par >> 2) & 1, py = (par >> 1) & 1, px = par & 1;
        int dz = (off >> 2) & 1, dy = (off >> 1) & 1, dx = off & 1;
        int sz = dz * (1 + pz), nz = (pz != dz) ? 2 : 1;
        int sy = dy * (1 + py), ny = (py != dy) ? 2 : 1;
        int sx = dx * (1 + px), nx = (px != dx) ? 2 : 1;
        float s = 0.f;
        for (int a = 0; a < nz; a++)
            for (int bb = 0; bb < ny; bb++)
                for (int cc = 0; cc < nx; cc++)
                    s += nlw[jc * 27 + ((sz + a) * 3 + (sy + bb)) * 3 + (sx + cc)];
        cw[e] = s;
    }
    __syncthreads();

    int gid = blockIdx.x * 256 + tid;        // 524288 output points
    int b   = gid >> 18;
    int rem = gid & 262143;
    int oz = rem >> 12, oy = (rem >> 6) & 63, ox = rem & 63;
    int par = ((oz & 1) << 2) | ((oy & 1) << 1) | (ox & 1);
    int bz = ((oz + 1) >> 1) - 1;
    int by = ((oy + 1) >> 1) - 1;
    int bx = ((ox + 1) >> 1) - 1;

    // load 8 cells x 3 channels (0 if OOB)
    float vals[8][3];
    const float* dgp = &g_dg[b * 3 * SP];
    #pragma unroll
    for (int off = 0; off < 8; off++) {
        int zi = bz + ((off >> 2) & 1);
        int yi = by + ((off >> 1) & 1);
        int xi = bx + (off & 1);
        bool ok = ((unsigned)zi < 32u) & ((unsigned)yi < 32u) & ((unsigned)xi < 32u);
        int s = zi * 1024 + yi * 32 + xi;
        vals[off][0] = ok ? dgp[s]          : 0.f;
        vals[off][1] = ok ? dgp[s + SP]     : 0.f;
        vals[off][2] = ok ? dgp[s + 2 * SP] : 0.f;
    }

    const float* cwp = &cw[par * 72];
    float a0 = bsm[0], a1 = bsm[1], a2 = bsm[2];
    #pragma unroll
    for (int off = 0; off < 8; off++) {
        const float* w9 = &cwp[off * 9];
        float v0 = vals[off][0], v1 = vals[off][1], v2 = vals[off][2];
        a0 = fmaf(w9[0], v0, a0); a0 = fmaf(w9[1], v1, a0); a0 = fmaf(w9[2], v2, a0);
        a1 = fmaf(w9[3], v0, a1); a1 = fmaf(w9[4], v1, a1); a1 = fmaf(w9[5], v2, a1);
        a2 = fmaf(w9[6], v0, a2); a2 = fmaf(w9[7], v1, a2); a2 = fmaf(w9[8], v2, a2);
    }

    int obase = oz * 4096 + oy * 64 + ox;
    out[(b * 3 + 0) * 262144 + obase] = a0;
    out[(b * 3 + 1) * 262144 + obase] = a1;
    out[(b * 3 + 2) * 262144 + obase] = a2;
}

// ---------------- launcher ----------------
extern "C" void kernel_launch(void* const* d_in, const int* in_sizes, int n_in,
                              void* d_out, int out_size) {
    const float* q    = (const float*)d_in[0];
    const float* k    = (const float*)d_in[1];
    const float* v    = (const float*)d_in[2];
    const float* gnw  = (const float*)d_in[3];
    const float* gnb  = (const float*)d_in[4];
    const float* outw = (const float*)d_in[5];
    const float* outb = (const float*)d_in[6];
    const float* dgw  = (const float*)d_in[7];
    const float* dgb  = (const float*)d_in[8];
    const float* nlw  = (const float*)d_in[9];
    const float* nlb  = (const float*)d_in[10];
    float* out = (float*)d_out;

    k_zero<<<768, 256>>>();
    k_stats<<<1536, 256>>>(q, k, v);
    k_norm_finalize<<<1, 256>>>(gnw, gnb);
    k_context<<<512, 256>>>(k, v);
    k_Mu<<<512, 256>>>(outw, outb);
    k_W2ct<<<162, 256>>>(dgw);
    dim3 g5(64, 4);
    k_dgconv<<<g5, 256>>>(q, dgb);
    k_upconv<<<2048, 256>>>(nlw, nlb, out);
}

// round 17
// speedup vs baseline: 2.3287x; 1.0578x over previous
#include <cuda_runtime.h>
#include <math.h>

// ---------------- problem constants ----------------
#define SP      32768          // 32*32*32 spatial
#define EPSV    1e-5f
#define TN      64             // n-tile in context kernel
#define NCHUNK  128
#define CHUNK_N (SP / NCHUNK)  // 256

// ---------------- scratch (device globals, no allocs) ----------------
__device__ float g_chanSum[3 * 2 * 256];
__device__ float g_chanSqs[3 * 2 * 256];
__device__ float g_chanMin[2 * 256];
__device__ float g_chanMax[2 * 256];
__device__ float g_scale[3 * 2 * 256];
__device__ float g_shift[3 * 2 * 256];
__device__ float g_rowmax[2 * 256];
__device__ float g_ctx[2 * 4 * 64 * 64];
__device__ float g_Z[2 * 4 * 64];
__device__ float g_M[2 * 256 * 256];
__device__ float g_u[2 * 256];
__device__ float g_W2[2 * 3 * 27 * 256];
__device__ float g_ct[2 * 3 * 27];
__device__ float g_dg[2 * 3 * SP];

// ---------------- f32x2 helpers ----------------
__device__ __forceinline__ unsigned long long pack2(float lo, float hi) {
    unsigned long long r;
    asm("mov.b64 %0, {%1, %2};" : "=l"(r) : "f"(lo), "f"(hi));
    return r;
}
__device__ __forceinline__ unsigned long long dup2(float v) {
    unsigned long long r;
    asm("mov.b64 %0, {%1, %1};" : "=l"(r) : "f"(v));
    return r;
}
__device__ __forceinline__ void fma2(unsigned long long& d, unsigned long long a,
                                     unsigned long long b) {
    asm("fma.rn.f32x2 %0, %1, %2, %0;" : "+l"(d) : "l"(a), "l"(b));
}
__device__ __forceinline__ void add2(unsigned long long& d, unsigned long long a) {
    asm("add.rn.f32x2 %0, %1, %0;" : "+l"(d) : "l"(a));
}
__device__ __forceinline__ void unpack2(unsigned long long v, float& lo, float& hi) {
    asm("mov.b64 {%0, %1}, %2;" : "=f"(lo), "=f"(hi) : "l"(v));
}

// ---------------- K1: per-channel stats (float4) + fused zeroing ----------------
__global__ void __launch_bounds__(256) k_stats(const float* __restrict__ q,
                                               const float* __restrict__ k,
                                               const float* __restrict__ v) {
    int bid = blockIdx.x;          // t*512 + b*256 + c
    int tid = threadIdx.x;

    // fused accumulator zeroing (first 768 blocks)
    if (bid < 768) {
        int i = bid * 256 + tid;
        if (i < 2 * 3 * SP)      g_dg[i]  = 0.f;
        if (i < 2 * 4 * 64 * 64) g_ctx[i] = 0.f;
        if (i < 2 * 4 * 64)      g_Z[i]   = 0.f;
    }

    int t   = bid >> 9;
    int bc  = bid & 511;
    const float* xp = (t == 0 ? q : (t == 1 ? k : v)) + (size_t)bc * SP;
    const float4* x4 = reinterpret_cast<const float4*>(xp);
    float s = 0.f, s2 = 0.f, mn = 3.4e38f, mx = -3.4e38f;
    #pragma unroll 4
    for (int i = tid; i < SP / 4; i += 256) {
        float4 u = x4[i];
        s += (u.x + u.y) + (u.z + u.w);
        s2 = fmaf(u.x, u.x, s2); s2 = fmaf(u.y, u.y, s2);
        s2 = fmaf(u.z, u.z, s2); s2 = fmaf(u.w, u.w, s2);
        mn = fminf(mn, fminf(fminf(u.x, u.y), fminf(u.z, u.w)));
        mx = fmaxf(mx, fmaxf(fmaxf(u.x, u.y), fmaxf(u.z, u.w)));
    }
    __shared__ float rs[256], rs2[256], rmn[256], rmx[256];
    rs[tid] = s; rs2[tid] = s2; rmn[tid] = mn; rmx[tid] = mx;
    __syncthreads();
    for (int o = 128; o > 0; o >>= 1) {
        if (tid < o) {
            rs[tid] += rs[tid + o]; rs2[tid] += rs2[tid + o];
            rmn[tid] = fminf(rmn[tid], rmn[tid + o]);
            rmx[tid] = fmaxf(rmx[tid], rmx[tid + o]);
        }
        __syncthreads();
    }
    if (tid == 0) {
        g_chanSum[bid] = rs[0];
        g_chanSqs[bid] = rs2[0];
        if (t == 1) { g_chanMin[bc] = rmn[0]; g_chanMax[bc] = rmx[0]; }
    }
}

// ---------------- K2: finalize GN affine + softmax row max ----------------
__global__ void k_norm_finalize(const float* __restrict__ gnw,
                                const float* __restrict__ gnb) {
    __shared__ float mu_s[3][2][4], rstd_s[3][2][4];
    int tid = threadIdx.x;
    if (tid < 24) {
        int t = tid >> 3, b = (tid >> 2) & 1, g = tid & 3;
        float s = 0.f, s2 = 0.f;
        int base = t * 512 + b * 256 + g * 64;
        for (int c = 0; c < 64; c++) { s += g_chanSum[base + c]; s2 += g_chanSqs[base + c]; }
        float n   = 64.0f * (float)SP;
        float mu  = s / n;
        float var = s2 / n - mu * mu;
        mu_s[t][b][g]   = mu;
        rstd_s[t][b][g] = rsqrtf(var + EPSV);
    }
    __syncthreads();
    int c = tid;
    int g = c >> 6;
    for (int t = 0; t < 3; t++)
        for (int b = 0; b < 2; b++) {
            float sc = gnw[c] * rstd_s[t][b][g];
            float sh = gnb[c] - mu_s[t][b][g] * sc;
            int idx = t * 512 + b * 256 + c;
            g_scale[idx] = sc;
            g_shift[idx] = sh;
            if (t == 1) {
                float rm = (sc >= 0.f) ? sc * g_chanMax[b * 256 + c]
                                       : sc * g_chanMin[b * 256 + c];
                g_rowmax[b * 256 + c] = rm + sh;
            }
        }
}

// ---------------- K3: context GEMM (64x64 per (b,h)) + softmax Z ----------------
__global__ void __launch_bounds__(256, 4) k_context(const float* __restrict__ kin,
                                                    const float* __restrict__ vin) {
    int blk   = blockIdx.x;                 // bh*NCHUNK + chunk
    int chunk = blk & (NCHUNK - 1);
    int bh    = blk >> 7;                   // b*4+h
    int b     = bh >> 2, h = bh & 3;
    int tid   = threadIdx.x;

    __shared__ __align__(16) float skm[TN * 68];   // exp(nk), [n][d]; reused as zred
    __shared__ __align__(16) float svm[TN * 68];   // nv,      [n][d]
    __shared__ float sK[64], cK[64], sV[64], cV[64];

    if (tid < 64) {
        int ch  = h * 64 + tid;
        int idx = b * 256 + ch;
        sK[tid] = g_scale[512 + idx];
        cK[tid] = g_shift[512 + idx] - g_rowmax[idx];
        sV[tid] = g_scale[1024 + idx];
        cV[tid] = g_shift[1024 + idx];
    }
    __syncthreads();

    const float* kbase = kin + ((size_t)(b * 256 + h * 64)) * SP + chunk * CHUNK_N;
    const float* vbase = vin + ((size_t)(b * 256 + h * 64)) * SP + chunk * CHUNK_N;

    int ty = tid >> 4, tx = tid & 15;
    int d0 = ty * 4,   e0 = tx * 4;

    unsigned long long acc[2][4];
    #pragma unroll
    for (int i = 0; i < 2; i++)
        #pragma unroll
        for (int j = 0; j < 4; j++) acc[i][j] = 0ull;
    unsigned long long z01 = 0ull, z23 = 0ull;

    for (int n0 = 0; n0 < CHUNK_N; n0 += TN) {
        #pragma unroll
        for (int i = 0; i < 16; i++) {
            int idx = tid + i * 256;
            int d = idx >> 6, n = idx & 63;
            float kv = kbase[(size_t)d * SP + n0 + n];
            float vv = vbase[(size_t)d * SP + n0 + n];
            skm[n * 68 + d] = __expf(fmaf(sK[d], kv, cK[d]));
            svm[n * 68 + d] = fmaf(sV[d], vv, cV[d]);
        }
        __syncthreads();
        #pragma unroll 4
        for (int n = 0; n < TN; n++) {
            ulonglong2 a = *reinterpret_cast<const ulonglong2*>(&skm[n * 68 + d0]);
            float4 vv    = *reinterpret_cast<const float4*>(&svm[n * 68 + e0]);
            unsigned long long v0 = dup2(vv.x), v1 = dup2(vv.y);
            unsigned long long v2 = dup2(vv.z), v3 = dup2(vv.w);
            fma2(acc[0][0], a.x, v0); fma2(acc[0][1], a.x, v1);
            fma2(acc[0][2], a.x, v2); fma2(acc[0][3], a.x, v3);
            fma2(acc[1][0], a.y, v0); fma2(acc[1][1], a.y, v1);
            fma2(acc[1][2], a.y, v2); fma2(acc[1][3], a.y, v3);
        }
        // Z partials (out of hot loop): this thread sums n = 4tx..4tx+3, rows d0..d0+3
        #pragma unroll
        for (int nn = 0; nn < 4; nn++) {
            ulonglong2 za = *reinterpret_cast<const ulonglong2*>(&skm[(tx * 4 + nn) * 68 + d0]);
            add2(z01, za.x); add2(z23, za.y);
        }
        __syncthreads();
    }

    // zred aliased onto skm (dead after mainloop; sync above separates uses)
    float* zred = skm;
    {
        float lo, hi;
        unpack2(z01, lo, hi);
        zred[(d0 + 0) * 16 + tx] = lo; zred[(d0 + 1) * 16 + tx] = hi;
        unpack2(z23, lo, hi);
        zred[(d0 + 2) * 16 + tx] = lo; zred[(d0 + 3) * 16 + tx] = hi;
    }
    __syncthreads();
    if (tid < 64) {
        float s = 0.f;
        #pragma unroll
        for (int i = 0; i < 16; i++) s += zred[tid * 16 + i];
        atomicAdd(&g_Z[bh * 64 + tid], s);
    }
    #pragma unroll
    for (int i = 0; i < 2; i++)
        #pragma unroll
        for (int j = 0; j < 4; j++) {
            float lo, hi;
            unpack2(acc[i][j], lo, hi);
            int e = e0 + j;
            atomicAdd(&g_ctx[(bh * 64 + d0 + 2 * i)     * 64 + e], lo);
            atomicAdd(&g_ctx[(bh * 64 + d0 + 2 * i + 1) * 64 + e], hi);
        }
}

// ---------------- K4a: M[b,o,c] and u[b,o] ----------------
__global__ void __launch_bounds__(256) k_Mu(const float* __restrict__ outw,
                                            const float* __restrict__ outb) {
    int b = blockIdx.x >> 8, o = blockIdx.x & 255;
    int c = threadIdx.x;
    __shared__ float wrow[256];
    wrow[c] = outw[o * 256 + c];
    __syncthreads();
    int h = c >> 6, d = c & 63;
    const float* ctxrow = &g_ctx[((b * 4 + h) * 64 + d) * 64];
    float zinv = 1.0f / g_Z[(b * 4 + h) * 64 + d];
    float m = 0.f;
    #pragma unroll 8
    for (int e = 0; e < 64; e++) m = fmaf(wrow[h * 64 + e], ctxrow[e], m);
    m *= zinv;
    g_M[(b * 256 + o) * 256 + c] = m;

    __shared__ float red[256];
    red[c] = m * g_shift[b * 256 + c];
    __syncthreads();
    for (int s = 128; s > 0; s >>= 1) {
        if (c < s) red[c] += red[c + s];
        __syncthreads();
    }
    if (c == 0) g_u[b * 256 + o] = outb[o] + red[0];
}

// ---------------- K4b: folded weights W2 and per-tap constants ct ----------------
__global__ void __launch_bounds__(256) k_W2ct(const float* __restrict__ dgw) {
    int bi = blockIdx.x;               // (b*3+j)*27 + t
    int t  = bi % 27;
    int bj = bi / 27;
    int b  = bj / 3, j = bj % 3;
    int c  = threadIdx.x;
    __shared__ float dcol[256];
    dcol[c] = dgw[(j * 256 + c) * 27 + t];
    __syncthreads();
    const float* Mp = &g_M[b * 256 * 256 + c];
    float a = 0.f;
    #pragma unroll 4
    for (int o = 0; o < 256; o++) a = fmaf(dcol[o], Mp[o * 256], a);
    g_W2[((b * 3 + j) * 27 + t) * 256 + c] = dcol[c] + g_scale[b * 256 + c] * a;

    __shared__ float red[256];
    red[c] = dcol[c] * g_u[b * 256 + c];
    __syncthreads();
    for (int s = 128; s > 0; s >>= 1) {
        if (c < s) red[c] += red[c + s];
        __syncthreads();
    }
    if (c == 0) g_ct[(b * 3 + j) * 27 + t] = red[0];
}

// ---------------- K5: folded 3x3x3 conv over raw q -> g_dg ----------------
// 256 threads: x(32) x yq(2) x zz(4); each thread computes 4 y-points.
// 8-way channel split (32 channels per blockIdx.y) for 512-CTA parallelism.
__global__ void __launch_bounds__(256) k_dgconv(const float* __restrict__ q,
                                                const float* __restrict__ dgbias) {
    int bx = blockIdx.x;               // b(2) * ztile(8) * ytile(4)
    int b  = bx >> 5;
    int r  = bx & 31;
    int z0 = (r >> 2) * 4;
    int y0 = (r & 3) * 8;
    int cg = blockIdx.y;               // 0..7, 32 channels each

    __shared__ float  qs[4 * 6 * 10 * 34];
    __shared__ __align__(16) float4 wd4[27 * 4];   // {w0,w0,w1,w1}
    __shared__ __align__(8)  float2 w2d[27 * 4];   // {w2,w2}
    __shared__ float cts[3 * 27];

    int tid = threadIdx.x;
    int x  = tid & 31;
    int yq = (tid >> 5) & 1;
    int zz = tid >> 6;

    if (tid < 81) cts[tid] = g_ct[b * 81 + tid];

    unsigned long long acc[3][2];
    #pragma unroll
    for (int j = 0; j < 3; j++) { acc[j][0] = 0ull; acc[j][1] = 0ull; }

    for (int ch = 0; ch < 8; ch++) {
        int cbase = cg * 32 + ch * 4;
        __syncthreads();
        if (tid < 108) {
            int t = tid >> 2, cc = tid & 3;
            int c = cbase + cc;
            float w0 = g_W2[((b * 3 + 0) * 27 + t) * 256 + c];
            float w1 = g_W2[((b * 3 + 1) * 27 + t) * 256 + c];
            float w2 = g_W2[((b * 3 + 2) * 27 + t) * 256 + c];
            wd4[tid] = make_float4(w0, w0, w1, w1);
            w2d[tid] = make_float2(w2, w2);
        }
        for (int it = tid; it < 8160; it += 256) {
            int c  = it / 2040;
            int r2 = it - c * 2040;
            int lz = r2 / 340;
            int r3 = r2 - lz * 340;
            int ly = r3 / 34;
            int lx = r3 - ly * 34;
            int gz = z0 - 1 + lz, gy = y0 - 1 + ly, gx = lx - 1;
            float val = 0.f;
            if ((unsigned)gz < 32u && (unsigned)gy < 32u && (unsigned)gx < 32u)
                val = q[((size_t)(b * 256 + cbase + c)) * SP + gz * 1024 + gy * 32 + gx];
            qs[it] = val;
        }
        __syncthreads();

        #pragma unroll
        for (int cc = 0; cc < 4; cc++) {
            #pragma unroll
            for (int kz = 0; kz < 3; kz++) {
                const float* qb = &qs[((cc * 6 + zz + kz) * 10 + yq * 4) * 34 + x];
                #pragma unroll
                for (int kx = 0; kx < 3; kx++) {
                    float q0 = qb[kx];
                    float q1 = qb[34 + kx];
                    float q2 = qb[68 + kx];
                    float q3 = qb[102 + kx];
                    float q4 = qb[136 + kx];
                    float q5 = qb[170 + kx];
                    unsigned long long Q01 = pack2(q0, q1);
                    unsigned long long Q12 = pack2(q1, q2);
                    unsigned long long Q23 = pack2(q2, q3);
                    unsigned long long Q34 = pack2(q3, q4);
                    unsigned long long Q45 = pack2(q4, q5);
                    #pragma unroll
                    for (int ky = 0; ky < 3; ky++) {
                        int wi = ((kz * 3 + ky) * 3 + kx) * 4 + cc;
                        ulonglong2 wu = *reinterpret_cast<const ulonglong2*>(&wd4[wi]);
                        unsigned long long w2u =
                            *reinterpret_cast<const unsigned long long*>(&w2d[wi]);
                        unsigned long long A = (ky == 0) ? Q01 : (ky == 1) ? Q12 : Q23;
                        unsigned long long B = (ky == 0) ? Q23 : (ky == 1) ? Q34 : Q45;
                        fma2(acc[0][0], A, wu.x); fma2(acc[0][1], B, wu.x);
                        fma2(acc[1][0], A, wu.y); fma2(acc[1][1], B, wu.y);
                        fma2(acc[2][0], A, w2u);  fma2(acc[2][1], B, w2u);
                    }
                }
            }
        }
    }

    int z = z0 + zz;
    float o[3][4];
    #pragma unroll
    for (int j = 0; j < 3; j++) {
        unpack2(acc[j][0], o[j][0], o[j][1]);
        unpack2(acc[j][1], o[j][2], o[j][3]);
    }

    if (cg == 0) {
        for (int j = 0; j < 3; j++)
            for (int py = 0; py < 4; py++) {
                int y = y0 + yq * 4 + py;
                float s = dgbias[j];
                for (int kz = 0; kz < 3; kz++) {
                    int gz = z + kz - 1;
                    if ((unsigned)gz >= 32u) continue;
                    for (int ky = 0; ky < 3; ky++) {
                        int gy = y + ky - 1;
                        if ((unsigned)gy >= 32u) continue;
                        for (int kx = 0; kx < 3; kx++) {
                            int gx = x + kx - 1;
                            if ((unsigned)gx >= 32u) continue;
                            s += cts[j * 27 + (kz * 3 + ky) * 3 + kx];
                        }
                    }
                }
                o[j][py] += s;
            }
    }
    #pragma unroll
    for (int j = 0; j < 3; j++)
        #pragma unroll
        for (int py = 0; py < 4; py++) {
            int y = y0 + yq * 4 + py;
            atomicAdd(&g_dg[(b * 3 + j) * SP + z * 1024 + y * 32 + x], o[j][py]);
        }
}

// ---------------- K6: fused 2x nearest-upsample + final 3x3x3 conv ----------------
__global__ void __launch_bounds__(256) k_upconv(const float* __restrict__ nlw,
                                                const float* __restrict__ nlb,
                                                float* __restrict__ out) {
    __shared__ float cw[576];     // [par(8)][off(8)][jc(9)]
    __shared__ float bsm[3];
    int tid = threadIdx.x;
    if (tid < 3) bsm[tid] = nlb[tid];
    for (int e = tid; e < 576; e += 256) {
        int jc  = e % 9;
        int off = (e / 9) & 7;
        int par = e / 72;
        int pz = (par >> 2) & 1, py = (par >> 1) & 1, px = par & 1;
        int dz = (off >> 2) & 1, dy = (off >> 1) & 1, dx = off & 1;
        int sz = dz * (1 + pz), nz = (pz != dz) ? 2 : 1;
        int sy = dy * (1 + py), ny = (py != dy) ? 2 : 1;
        int sx = dx * (1 + px), nx = (px != dx) ? 2 : 1;
        float s = 0.f;
        for (int a = 0; a < nz; a++)
            for (int bb = 0; bb < ny; bb++)
                for (int cc = 0; cc < nx; cc++)
                    s += nlw[jc * 27 + ((sz + a) * 3 + (sy + bb)) * 3 + (sx + cc)];
        cw[e] = s;
    }
    __syncthreads();

    int gid = blockIdx.x * 256 + tid;        // 524288 output points
    int b   = gid >> 18;
    int rem = gid & 262143;
    int oz = rem >> 12, oy = (rem >> 6) & 63, ox = rem & 63;
    int par = ((oz & 1) << 2) | ((oy & 1) << 1) | (ox & 1);
    int bz = ((oz + 1) >> 1) - 1;
    int by = ((oy + 1) >> 1) - 1;
    int bx = ((ox + 1) >> 1) - 1;

    float vals[8][3];
    const float* dgp = &g_dg[b * 3 * SP];
    #pragma unroll
    for (int off = 0; off < 8; off++) {
        int zi = bz + ((off >> 2) & 1);
        int yi = by + ((off >> 1) & 1);
        int xi = bx + (off & 1);
        bool ok = ((unsigned)zi < 32u) & ((unsigned)yi < 32u) & ((unsigned)xi < 32u);
        int s = zi * 1024 + yi * 32 + xi;
        vals[off][0] = ok ? dgp[s]          : 0.f;
        vals[off][1] = ok ? dgp[s + SP]     : 0.f;
        vals[off][2] = ok ? dgp[s + 2 * SP] : 0.f;
    }

    const float* cwp = &cw[par * 72];
    float a0 = bsm[0], a1 = bsm[1], a2 = bsm[2];
    #pragma unroll
    for (int off = 0; off < 8; off++) {
        const float* w9 = &cwp[off * 9];
        float v0 = vals[off][0], v1 = vals[off][1], v2 = vals[off][2];
        a0 = fmaf(w9[0], v0, a0); a0 = fmaf(w9[1], v1, a0); a0 = fmaf(w9[2], v2, a0);
        a1 = fmaf(w9[3], v0, a1); a1 = fmaf(w9[4], v1, a1); a1 = fmaf(w9[5], v2, a1);
        a2 = fmaf(w9[6], v0, a2); a2 = fmaf(w9[7], v1, a2); a2 = fmaf(w9[8], v2, a2);
    }

    int obase = oz * 4096 + oy * 64 + ox;
    out[(b * 3 + 0) * 262144 + obase] = a0;
    out[(b * 3 + 1) * 262144 + obase] = a1;
    out[(b * 3 + 2) * 262144 + obase] = a2;
}

// ---------------- launcher ----------------
extern "C" void kernel_launch(void* const* d_in, const int* in_sizes, int n_in,
                              void* d_out, int out_size) {
    const float* q    = (const float*)d_in[0];
    const float* k    = (const float*)d_in[1];
    const float* v    = (const float*)d_in[2];
    const float* gnw  = (const float*)d_in[3];
    const float* gnb  = (const float*)d_in[4];
    const float* outw = (const float*)d_in[5];
    const float* outb = (const float*)d_in[6];
    const float* dgw  = (const float*)d_in[7];
    const float* dgb  = (const float*)d_in[8];
    const float* nlw  = (const float*)d_in[9];
    const float* nlb  = (const float*)d_in[10];
    float* out = (float*)d_out;

    k_stats<<<1536, 256>>>(q, k, v);
    k_norm_finalize<<<1, 256>>>(gnw, gnb);
    k_context<<<1024, 256>>>(k, v);
    k_Mu<<<512, 256>>>(outw, outb);
    k_W2ct<<<162, 256>>>(dgw);
    dim3 g5(64, 8);
    k_dgconv<<<g5, 256>>>(q, dgb);
    k_upconv<<<2048, 256>>>(nlw, nlb, out);
}